// round 15
// baseline (speedup 1.0000x reference)
#include <cuda_runtime.h>
#include <cuda_fp16.h>
#include <math.h>
#include <stdint.h>

// Problem constants
#define Cc 256
#define Vv 17
#define Tt 256
#define Nr 1024            // B*T
#define Pp 17408           // Nr*Vv
#define DIN 1024
#define TOTAL 4456448      // B*C*V*T
#define INV_SQRT_DK 0.17677669529663687f

// 0-indexed adjacency (padded), degrees
__constant__ int c_nbr[17][5] = {
    {0,1,2,5,6},{0,1,3,0,0},{0,2,4,0,0},{1,3,0,0,0},{2,4,0,0,0},
    {0,5,7,11,0},{0,6,8,12,0},{5,7,9,0,0},{6,8,12,0,0},{7,9,0,0,0},
    {8,10,0,0,0},{8,11,13,0,0},{10,12,14,0,0},{11,13,15,0,0},{12,14,16,0,0},
    {13,15,0,0,0},{14,16,0,0,0}
};
__constant__ int c_deg[17] = {5,3,3,2,2,4,4,3,3,2,2,3,3,3,3,2,2};

// fp32 scratch
__device__ float g_X[Pp*Cc];
__device__ float g_xn[Pp*Cc];
__device__ float g_QKV[Pp*3*Cc];
__device__ float g_AKV[Pp*2*Cc];
__device__ float g_AKVr[Nr*2*Cc];
__device__ float g_y1[Pp*Cc];
__device__ float g_F[Pp*Cc];
__device__ float g_bj[2*3*Cc];
__device__ float g_stats[2*Cc];
// fp16 hi/lo activation scratch (A operands) + fp16 weights (W operands)
__device__ __half g_Eh[Pp*Cc],  g_El[Pp*Cc];
__device__ __half g_Rh[Nr*Cc],  g_Rl[Nr*Cc];
__device__ __half g_xnh[Pp*Cc], g_xnl[Pp*Cc];
__device__ __half g_reth[Pp*Cc], g_retl[Pp*Cc];
__device__ __half g_Hh[Pp*DIN], g_Hl[Pp*DIN];
__device__ __half g_Wj[2*3*Cc*Cc];
__device__ __half g_F1[2*DIN*Cc];
__device__ __half g_F2[2*Cc*DIN];

// ---------------- helpers ----------------
__device__ __forceinline__ uint32_t smem_u32(const void* p) {
    return (uint32_t)__cvta_generic_to_shared(p);
}
__device__ __forceinline__ void cpa16(uint32_t d, const void* s) {
    asm volatile("cp.async.cg.shared.global [%0], [%1], 16;" :: "r"(d), "l"(s));
}
#define CP_COMMIT() asm volatile("cp.async.commit_group;" ::: "memory")
#define CP_WAIT1()  asm volatile("cp.async.wait_group 1;" ::: "memory")
__device__ __forceinline__ void ldsm4(uint32_t* r, uint32_t a) {
    asm volatile("ldmatrix.sync.aligned.m8n8.x4.shared.b16 {%0,%1,%2,%3}, [%4];"
                 : "=r"(r[0]), "=r"(r[1]), "=r"(r[2]), "=r"(r[3]) : "r"(a));
}
__device__ __forceinline__ void mma_f16(float* c, const uint32_t* a, const uint32_t* b) {
    asm volatile("mma.sync.aligned.m16n8k16.row.col.f32.f16.f16.f32 "
                 "{%0,%1,%2,%3}, {%4,%5,%6,%7}, {%8,%9}, {%0,%1,%2,%3};"
                 : "+f"(c[0]), "+f"(c[1]), "+f"(c[2]), "+f"(c[3])
                 : "r"(a[0]), "r"(a[1]), "r"(a[2]), "r"(a[3]), "r"(b[0]), "r"(b[1]));
}
__device__ __forceinline__ void f2hl(float v, __half& h, __half& l) {
    h = __float2half_rn(v);
    l = __float2half_rn(v - __half2float(h));
}

// ---------------- tensor-core GEMM body (mma.sync fp16x2), 3-stage ----------------
// out = A @ W^T; A[M,K] split hi/lo fp16, W[N,K] fp16, K-major.
// M%128==0, N%128==0, K%32==0. Residual (optional) given as hi/lo fp16 pair.
#define BK 32
#define TSTRIDE 80                      // padded bytes per smem row (conflict-free ldmatrix)
#define TILE_BYTES (128*TSTRIDE)        // 10240
#define STAGE_BYTES (3*TILE_BYTES)      // 30720
#define NSTAGE 3
#define GEMM_SMEM (NSTAGE*STAGE_BYTES)  // 92160 -> 2 CTAs/SM

__device__ __forceinline__ void gemm_body(
    const __half* __restrict__ Ah, const __half* __restrict__ Al,
    const __half* __restrict__ W,
    const float* __restrict__ bias,
    const __half* __restrict__ resh, const __half* __restrict__ resl,
    float* __restrict__ outf, __half* __restrict__ outh, __half* __restrict__ outl,
    int N, int K, int relu, int bm, int bn, char* smem_gen)
{
    const uint32_t sb = smem_u32(smem_gen);
    const int tid = threadIdx.x;
    const int warp = tid >> 5, lane = tid & 31;
    const int wm = (warp >> 1) * 32;
    const int wn = (warp & 1) * 64;

    const __half* srcs[3] = {
        Ah + (size_t)bm * K, Al + (size_t)bm * K, W + (size_t)bn * K
    };

    auto load_stage = [&](int stage, int kc) {
        const uint32_t base = sb + stage * STAGE_BYTES;
        const int k0 = kc * BK;
        #pragma unroll
        for (int t2 = 0; t2 < 3; t2++) {
            const uint32_t tb = base + t2 * TILE_BYTES;
            const __half* s = srcs[t2] + k0;
            #pragma unroll
            for (int u0 = 0; u0 < 2; u0++) {
                int u = tid + u0 * 256;          // 512 units: 128 rows x 4 16B-chunks
                int row = u >> 2, ch = u & 3;
                cpa16(tb + row * TSTRIDE + ch * 16, s + (size_t)row * K + ch * 8);
            }
        }
    };

    float acc[2][8][4] = {};
    const int NCK = K / BK;

    load_stage(0, 0);
    CP_COMMIT();
    if (NCK > 1) load_stage(1, 1);
    CP_COMMIT();

    int stage = 0;
    for (int kc = 0; kc < NCK; kc++) {
        CP_WAIT1();
        __syncthreads();

        int nst = stage + 2; if (nst >= NSTAGE) nst -= NSTAGE;
        if (kc + 2 < NCK) load_stage(nst, kc + 2);
        CP_COMMIT();

        const uint32_t base = sb + stage * STAGE_BYTES;
        const uint32_t A_h = base;
        const uint32_t A_l = base + TILE_BYTES;
        const uint32_t W_s = base + 2 * TILE_BYTES;

        #pragma unroll
        for (int fk = 0; fk < 2; fk++) {
            uint32_t ah[2][4], al[2][4];
            {
                int arow = wm + (lane & 15);
                int abyte = fk * 32 + ((lane >> 4) << 4);
                ldsm4(ah[0], A_h + arow * TSTRIDE + abyte);
                ldsm4(ah[1], A_h + (arow + 16) * TSTRIDE + abyte);
                ldsm4(al[0], A_l + arow * TSTRIDE + abyte);
                ldsm4(al[1], A_l + (arow + 16) * TSTRIDE + abyte);
            }
            uint32_t wv[8][2];
            {
                int brow = wn + ((lane & 16) >> 1) + (lane & 7);
                int bbyte = fk * 32 + (((lane >> 3) & 1) << 4);
                #pragma unroll
                for (int fo = 0; fo < 4; fo++) {
                    uint32_t r[4];
                    ldsm4(r, W_s + (brow + fo * 16) * TSTRIDE + bbyte);
                    wv[2 * fo][0] = r[0]; wv[2 * fo][1] = r[1];
                    wv[2 * fo + 1][0] = r[2]; wv[2 * fo + 1][1] = r[3];
                }
            }
            #pragma unroll
            for (int fm = 0; fm < 2; fm++)
                #pragma unroll
                for (int fn = 0; fn < 8; fn++) {
                    mma_f16(acc[fm][fn], ah[fm], wv[fn]);   // hi*W
                    mma_f16(acc[fm][fn], al[fm], wv[fn]);   // lo*W
                }
        }
        stage++; if (stage >= NSTAGE) stage = 0;
    }

    // ---------------- epilogue ----------------
    #pragma unroll
    for (int fm = 0; fm < 2; fm++) {
        #pragma unroll
        for (int fn = 0; fn < 8; fn++) {
            int r0 = bm + wm + fm * 16 + (lane >> 2);
            int c  = bn + wn + fn * 8 + (lane & 3) * 2;
            #pragma unroll
            for (int half_ = 0; half_ < 2; half_++) {
                size_t row = (size_t)(r0 + half_ * 8);
                float v0 = acc[fm][fn][half_ * 2];
                float v1 = acc[fm][fn][half_ * 2 + 1];
                if (bias) { v0 += bias[c]; v1 += bias[c + 1]; }
                if (resh) {
                    __half2 rh = *(const __half2*)(resh + row * N + c);
                    __half2 rl = *(const __half2*)(resl + row * N + c);
                    v0 += __half2float(rh.x) + __half2float(rl.x);
                    v1 += __half2float(rh.y) + __half2float(rl.y);
                }
                if (relu) { v0 = fmaxf(v0, 0.f); v1 = fmaxf(v1, 0.f); }
                if (outf) *(float2*)(outf + row * N + c) = make_float2(v0, v1);
                if (outh) {
                    __half h0, l0, h1, l1;
                    f2hl(v0, h0, l0); f2hl(v1, h1, l1);
                    *(__half2*)(outh + row * N + c) = __halves2half2(h0, h1);
                    *(__half2*)(outl + row * N + c) = __halves2half2(l0, l1);
                }
            }
        }
    }
}

// standard GEMM kernel (FFN1 / FFN2); min 2 blocks/SM pins regs <= 128
__global__ void __launch_bounds__(256, 2) gemm_mma(
    const __half* __restrict__ Ah, const __half* __restrict__ Al,
    const __half* __restrict__ W,
    const float* __restrict__ bias,
    const __half* __restrict__ resh, const __half* __restrict__ resl,
    float* __restrict__ outf,
    __half* __restrict__ outh, __half* __restrict__ outl,
    int N, int K, int relu, float* __restrict__ zstats)
{
    extern __shared__ char smem[];
    const int bm = blockIdx.y * 128;
    const int bn = blockIdx.x * 128;
    // fold bn_zero into this launch (block (0,0); prior stats consumer already retired)
    if (zstats && bm == 0 && bn == 0) {
        zstats[threadIdx.x] = 0.f;
        zstats[256 + threadIdx.x] = 0.f;
    }
    gemm_body(Ah, Al, W, bias, resh, resl, outf, outh, outl, N, K, relu, bm, bn, smem);
}

// batched projection GEMM: QKV (816 blocks) + AKV (544) + AKVr (32), K=256
#define PROJ_BLOCKS (816 + 544 + 32)
__global__ void __launch_bounds__(256, 2) gemm_proj3(
    const __half* __restrict__ xnh, const __half* __restrict__ xnl,
    const __half* __restrict__ Eh,  const __half* __restrict__ El,
    const __half* __restrict__ Rh,  const __half* __restrict__ Rl,
    const __half* __restrict__ Wqkv, const float* __restrict__ bqkv,
    float* __restrict__ QKV, float* __restrict__ AKV, float* __restrict__ AKVr)
{
    extern __shared__ char smem[];
    int bid = blockIdx.x;
    const __half *Ah, *Al, *W;
    const float* bias;
    float* outf;
    int N, bm, bn;
    if (bid < 816) {                 // QKV: [Pp,768] = xn @ Wqkv^T
        Ah = xnh; Al = xnl; W = Wqkv; bias = bqkv; outf = QKV; N = 768;
        bm = (bid / 6) * 128; bn = (bid % 6) * 128;
    } else if (bid < 816 + 544) {    // AKe|AVe: [Pp,512] = embs @ Wkv^T
        int t = bid - 816;
        Ah = Eh; Al = El; W = Wqkv + (size_t)Cc * Cc; bias = bqkv + Cc;
        outf = AKV; N = 512;
        bm = (t / 4) * 128; bn = (t % 4) * 128;
    } else {                         // AKr|AVr: [Nr,512] = relay0 @ Wkv^T
        int t = bid - 816 - 544;
        Ah = Rh; Al = Rl; W = Wqkv + (size_t)Cc * Cc; bias = bqkv + Cc;
        outf = AKVr; N = 512;
        bm = (t / 4) * 128; bn = (t % 4) * 128;
    }
    gemm_body(Ah, Al, W, bias, nullptr, nullptr, outf, nullptr, nullptr, N, Cc, 0,
              bm, bn, smem);
}

// ---------------- merged layout prep + relay init (one launch) ----------------
// idx < TOTAL: transpose data -> X + hi/lo embs.  idx >= TOTAL: relay0 (mean over v).
#define PREP_TOTAL (TOTAL + Nr * Cc)
__global__ void prep_all(const float* __restrict__ data, float* __restrict__ X,
                         __half* __restrict__ Eh, __half* __restrict__ El,
                         __half* __restrict__ Rh, __half* __restrict__ Rl)
{
    int idx = blockIdx.x * blockDim.x + threadIdx.x;
    if (idx < TOTAL) {
        int t = idx % Tt;
        int v = (idx / Tt) % Vv;
        int c = (idx / (Tt * Vv)) % Cc;
        int b = idx / (Tt * Vv * Cc);
        float val = data[idx];
        size_t o = (size_t)((b * Tt + t) * Vv + v) * Cc + c;
        X[o] = val;
        f2hl(val, Eh[o], El[o]);
    } else if (idx < PREP_TOTAL) {
        int j = idx - TOTAL;
        int n = j >> 8;
        int c = j & 255;
        int b = n / Tt, t = n - b * Tt;
        float s = 0.f;
        #pragma unroll
        for (int v = 0; v < Vv; v++)
            s += data[(size_t)((b * Cc + c) * Vv + v) * Tt + t];
        f2hl(s * (1.0f / Vv), Rh[j], Rl[j]);
    }
}

// ---------------- merged weight prep (both layers, one launch) ----------------
#define WPREP_TOTAL 720896
__global__ void wprep2(const float* __restrict__ jq, const float* __restrict__ jk,
                       const float* __restrict__ jv,
                       const float* __restrict__ jqb, const float* __restrict__ jkb,
                       const float* __restrict__ jvb,
                       const float* __restrict__ jf1, const float* __restrict__ jf2,
                       __half* __restrict__ Wp, float* __restrict__ b,
                       __half* __restrict__ F1p, __half* __restrict__ F2p)
{
    int gidx = blockIdx.x * blockDim.x + threadIdx.x;
    if (gidx >= 2 * WPREP_TOTAL) return;
    int ly = gidx >= WPREP_TOTAL;
    int idx = gidx - ly * WPREP_TOTAL;
    const float* q  = jq + (size_t)ly * Cc * Cc;
    const float* k  = jk + (size_t)ly * Cc * Cc;
    const float* v  = jv + (size_t)ly * Cc * Cc;
    const float* f1 = jf1 + (size_t)ly * DIN * Cc;
    const float* f2 = jf2 + (size_t)ly * Cc * DIN;
    __half* Wl  = Wp + (size_t)ly * 3 * Cc * Cc;
    __half* F1l = F1p + (size_t)ly * DIN * Cc;
    __half* F2l = F2p + (size_t)ly * Cc * DIN;
    float* bl   = b + (size_t)ly * 3 * Cc;
    if (idx < 3 * Cc) {
        const float* qb = jqb + ly * Cc;
        const float* kb = jkb + ly * Cc;
        const float* vb = jvb + ly * Cc;
        bl[idx] = (idx < Cc) ? qb[idx] : (idx < 2 * Cc) ? kb[idx - Cc] : vb[idx - 2 * Cc];
    }
    if (idx < 3 * Cc * Cc) {
        int row = idx >> 8;
        int col = idx & 255;
        const float* src = (row < Cc) ? q + (size_t)row * Cc
                         : (row < 2 * Cc) ? k + (size_t)(row - Cc) * Cc
                         : v + (size_t)(row - 2 * Cc) * Cc;
        Wl[idx] = __float2half_rn(src[col]);
    } else if (idx < 3 * Cc * Cc + DIN * Cc) {
        int i = idx - 3 * Cc * Cc;
        F1l[i] = __float2half_rn(f1[i]);
    } else {
        int i = idx - 3 * Cc * Cc - DIN * Cc;
        F2l[i] = __float2half_rn(f2[i]);
    }
}

// ---------------- LayerNorm (layer-0 entry: reads X) ----------------
__global__ void __launch_bounds__(256) ln_kernel(const float* __restrict__ x,
                                                 const float* __restrict__ g,
                                                 const float* __restrict__ b,
                                                 float* __restrict__ y,
                                                 __half* __restrict__ yh,
                                                 __half* __restrict__ yl)
{
    int row = blockIdx.x * 8 + (threadIdx.x >> 5);
    int lane = threadIdx.x & 31;
    const float* xr = x + (size_t)row * Cc;
    float v[8];
    float s = 0.f;
    #pragma unroll
    for (int i = 0; i < 8; i++) { v[i] = xr[lane + 32 * i]; s += v[i]; }
    #pragma unroll
    for (int o = 16; o; o >>= 1) s += __shfl_xor_sync(~0u, s, o);
    float mean = s * (1.0f / Cc);
    float s2 = 0.f;
    #pragma unroll
    for (int i = 0; i < 8; i++) { float d = v[i] - mean; s2 += d * d; }
    #pragma unroll
    for (int o = 16; o; o >>= 1) s2 += __shfl_xor_sync(~0u, s2, o);
    float rs = rsqrtf(s2 * (1.0f / Cc) + 1e-6f);
    #pragma unroll
    for (int i = 0; i < 8; i++) {
        int c = lane + 32 * i;
        size_t o = (size_t)row * Cc + c;
        float yv = (v[i] - mean) * rs * g[c] + b[c];
        y[o] = yv;
        f2hl(yv, yh[o], yl[o]);
    }
}

// ---------------- fused BN(leaky) + LN  (layer boundary; skips X round-trip) --------
__global__ void __launch_bounds__(256) bnln_kernel(const float* __restrict__ F,
                                                   const float* __restrict__ stats,
                                                   const float* __restrict__ fg,
                                                   const float* __restrict__ fb,
                                                   const float* __restrict__ lg,
                                                   const float* __restrict__ lb,
                                                   float* __restrict__ y,
                                                   __half* __restrict__ yh,
                                                   __half* __restrict__ yl)
{
    int row = blockIdx.x * 8 + (threadIdx.x >> 5);
    int lane = threadIdx.x & 31;
    const float* xr = F + (size_t)row * Cc;
    const float inv = 1.0f / Pp;
    float v[8];
    float s = 0.f;
    #pragma unroll
    for (int i = 0; i < 8; i++) {
        int c = lane + 32 * i;
        float mean = stats[c] * inv;
        float var = stats[Cc + c] * inv - mean * mean;
        float t = (xr[c] - mean) * rsqrtf(var + 1e-5f) * fg[c] + fb[c];
        t = t > 0.f ? t : 0.01f * t;          // leaky
        v[i] = t;
        s += t;
    }
    #pragma unroll
    for (int o = 16; o; o >>= 1) s += __shfl_xor_sync(~0u, s, o);
    float mean = s * (1.0f / Cc);
    float s2 = 0.f;
    #pragma unroll
    for (int i = 0; i < 8; i++) { float d = v[i] - mean; s2 += d * d; }
    #pragma unroll
    for (int o = 16; o; o >>= 1) s2 += __shfl_xor_sync(~0u, s2, o);
    float rs = rsqrtf(s2 * (1.0f / Cc) + 1e-6f);
    #pragma unroll
    for (int i = 0; i < 8; i++) {
        int c = lane + 32 * i;
        size_t o = (size_t)row * Cc + c;
        float yv = (v[i] - mean) * rs * lg[c] + lb[c];
        y[o] = yv;
        f2hl(yv, yh[o], yl[o]);
    }
}

// ---------------- fused BN(leaky) + output transpose (final layer) ----------------
__global__ void __launch_bounds__(256) bnfinal_kernel(const float* __restrict__ F,
                                                      const float* __restrict__ stats,
                                                      const float* __restrict__ g,
                                                      const float* __restrict__ b,
                                                      float* __restrict__ out)
{
    int idx = blockIdx.x * blockDim.x + threadIdx.x;
    if (idx >= TOTAL) return;
    int t = idx % Tt;
    int v = (idx / Tt) % Vv;
    int c = (idx / (Tt * Vv)) % Cc;
    int bb = idx / (Tt * Vv * Cc);
    float f = F[(size_t)((bb * Tt + t) * Vv + v) * Cc + c];
    const float inv = 1.0f / Pp;
    float mean = stats[c] * inv;
    float var = stats[Cc + c] * inv - mean * mean;
    float val = (f - mean) * rsqrtf(var + 1e-5f) * g[c] + b[c];
    out[idx] = val > 0.f ? val : 0.01f * val;
}

// ---------------- graph attention (7 slots), packed inputs ----------------
__global__ void __launch_bounds__(256) attn_j(const float* __restrict__ QKV,
                                              const float* __restrict__ AKV,
                                              const float* __restrict__ AKVr,
                                              const float* __restrict__ xn,
                                              float* __restrict__ y1,
                                              float* __restrict__ zstats)
{
    int p = blockIdx.x;
    int co = threadIdx.x;
    if (p == 0) { zstats[co] = 0.f; zstats[256 + co] = 0.f; }   // fold bn_zero
    int n = p / Vv, l = p - n * Vv;
    size_t qbase = (size_t)p * 768 + co;
    size_t abase = (size_t)p * 512 + co;
    size_t rbase = (size_t)n * 512 + co;
    float q = QKV[qbase];
    int deg = c_deg[l];
    float sc[7];
    #pragma unroll
    for (int w = 0; w < 5; w++) {
        float d = -1e30f;
        if (w < deg) {
            int j = c_nbr[l][w];
            float dd = q * QKV[(size_t)(n * Vv + j) * 768 + 256 + co];
            #pragma unroll
            for (int o = 16; o; o >>= 1) dd += __shfl_xor_sync(~0u, dd, o);
            d = dd * INV_SQRT_DK;
        }
        sc[w] = d;
    }
    {
        float dd = q * AKV[abase];
        #pragma unroll
        for (int o = 16; o; o >>= 1) dd += __shfl_xor_sync(~0u, dd, o);
        sc[5] = dd * INV_SQRT_DK;
        dd = q * AKVr[rbase];
        #pragma unroll
        for (int o = 16; o; o >>= 1) dd += __shfl_xor_sync(~0u, dd, o);
        sc[6] = dd * INV_SQRT_DK;
    }
    float mx = sc[0];
    #pragma unroll
    for (int w = 1; w < 7; w++) mx = fmaxf(mx, sc[w]);
    float wg[7];
    float sum = 0.f;
    #pragma unroll
    for (int w = 0; w < 7; w++) { wg[w] = expf(sc[w] - mx); sum += wg[w]; }
    float att = 0.f;
    #pragma unroll
    for (int w = 0; w < 5; w++)
        if (w < deg) att += wg[w] * QKV[(size_t)(n * Vv + c_nbr[l][w]) * 768 + 512 + co];
    att += wg[5] * AKV[abase + 256] + wg[6] * AKVr[rbase + 256];
    y1[(size_t)p * Cc + co] = xn[(size_t)p * Cc + co] + att / sum;
}

// ---------------- BatchNorm (axes 0,2) ----------------
__global__ void __launch_bounds__(256) bn_stats(const float* __restrict__ x,
                                                float* __restrict__ stats, int rows)
{
    int c = threadIdx.x;
    int r0 = blockIdx.x * 64;
    float s = 0.f, s2 = 0.f;
    for (int r = r0; r < r0 + 64; r++) {
        float v = x[(size_t)r * Cc + c];
        s += v; s2 += v * v;
    }
    atomicAdd(&stats[c], s);
    atomicAdd(&stats[Cc + c], s2);
}

__global__ void __launch_bounds__(256) bn_apply(const float* __restrict__ x,
                                                const float* __restrict__ stats,
                                                const float* __restrict__ g,
                                                const float* __restrict__ b,
                                                __half* __restrict__ yh,
                                                __half* __restrict__ yl,
                                                int rows, int leaky)
{
    int idx = blockIdx.x * blockDim.x + threadIdx.x;
    if (idx >= rows * Cc) return;
    int c = idx & 255;
    float inv = 1.0f / rows;
    float mean = stats[c] * inv;
    float var = stats[Cc + c] * inv - mean * mean;
    float v = (x[idx] - mean) * rsqrtf(var + 1e-5f) * g[c] + b[c];
    if (leaky) v = v > 0.f ? v : 0.01f * v;
    f2hl(v, yh[idx], yl[idx]);
}

// ---------------- host ----------------
template <typename Sym>
static float* sym_f(const Sym& s) { void* p = nullptr; cudaGetSymbolAddress(&p, s); return (float*)p; }
template <typename Sym>
static __half* sym_h(const Sym& s) { void* p = nullptr; cudaGetSymbolAddress(&p, s); return (__half*)p; }

extern "C" void kernel_launch(void* const* d_in, const int* in_sizes, int n_in,
                              void* d_out, int out_size)
{
    const float* data  = (const float*)d_in[0];
    const float* ln_g  = (const float*)d_in[1];
    const float* ln_b  = (const float*)d_in[2];
    const float* jq_w  = (const float*)d_in[3];
    const float* jq_b  = (const float*)d_in[4];
    const float* jk_w  = (const float*)d_in[5];
    const float* jk_b  = (const float*)d_in[6];
    const float* jv_w  = (const float*)d_in[7];
    const float* jv_b  = (const float*)d_in[8];
    const float* jbn_g = (const float*)d_in[9];
    const float* jbn_b = (const float*)d_in[10];
    const float* jf1_w = (const float*)d_in[11];
    const float* jf1_b = (const float*)d_in[12];
    const float* jf2_w = (const float*)d_in[13];
    const float* jf2_b = (const float*)d_in[14];
    const float* jfbn_g = (const float*)d_in[15];
    const float* jfbn_b = (const float*)d_in[16];
    // relay-path weights (d_in[17..30]) are dead: relay never feeds back into nodes.

    float* X    = sym_f(g_X);
    float* xn   = sym_f(g_xn);
    float* QKV  = sym_f(g_QKV);
    float* AKV  = sym_f(g_AKV);
    float* AKVr = sym_f(g_AKVr);
    float* y1   = sym_f(g_y1);
    float* F    = sym_f(g_F);
    float* bj   = sym_f(g_bj);
    float* stats = sym_f(g_stats);
    __half *Eh = sym_h(g_Eh), *El = sym_h(g_El);
    __half *Rh = sym_h(g_Rh), *Rl = sym_h(g_Rl);
    __half *xnh = sym_h(g_xnh), *xnl = sym_h(g_xnl);
    __half *reth = sym_h(g_reth), *retl = sym_h(g_retl);
    __half *Hh = sym_h(g_Hh), *Hl = sym_h(g_Hl);
    __half *Wj = sym_h(g_Wj);
    __half *F1 = sym_h(g_F1);
    __half *F2 = sym_h(g_F2);

    static bool attr_set = false;
    if (!attr_set) {
        cudaFuncSetAttribute(gemm_mma, cudaFuncAttributeMaxDynamicSharedMemorySize, GEMM_SMEM);
        cudaFuncSetAttribute(gemm_proj3, cudaFuncAttributeMaxDynamicSharedMemorySize, GEMM_SMEM);
        attr_set = true;
    }

    // merged transpose + relay init (launch 0)
    prep_all<<<(PREP_TOTAL + 255) / 256, 256>>>(data, X, Eh, El, Rh, Rl);

    wprep2<<<(2 * WPREP_TOTAL + 255) / 256, 256>>>(
        jq_w, jk_w, jv_w, jq_b, jk_b, jv_b, jf1_w, jf2_w,
        Wj, bj, F1, F2);

    // layer-0 entry LN reads X
    ln_kernel<<<Pp / 8, 256>>>(X, ln_g, ln_b, xn, xnh, xnl);

    for (int ly = 0; ly < 2; ly++) {
        const __half* Wl = Wj + (size_t)ly * 3 * Cc * Cc;
        const float* bl  = bj + (size_t)ly * 3 * Cc;
        const float* bng = jbn_g + ly * Cc;
        const float* bnb = jbn_b + ly * Cc;
        const __half* f1p = F1 + (size_t)ly * DIN * Cc;
        const float* f1b = jf1_b + ly * DIN;
        const __half* f2p = F2 + (size_t)ly * Cc * DIN;
        const float* f2b = jf2_b + ly * Cc;
        const float* fbg = jfbn_g + ly * Cc;
        const float* fbb = jfbn_b + ly * Cc;

        // all three projections in ONE launch (QKV | AKV | AKVr) — launch index 3 on ly=0
        gemm_proj3<<<PROJ_BLOCKS, 256, GEMM_SMEM>>>(
            xnh, xnl, Eh, El, Rh, Rl, Wl, bl, QKV, AKV, AKVr);

        attn_j<<<Pp, 256>>>(QKV, AKV, AKVr, xn, y1, stats);   // zeroes stats (block 0)

        bn_stats<<<Pp / 64, 256>>>(y1, stats, Pp);
        bn_apply<<<(Pp * Cc + 255) / 256, 256>>>(y1, stats, bng, bnb, reth, retl, Pp, 0);

        // FFN1: H = relu(ret @ f1^T + b1), written directly as hi/lo fp16
        gemm_mma<<<dim3(DIN / 128, Pp / 128), 256, GEMM_SMEM>>>(
            reth, retl, f1p, f1b, nullptr, nullptr, nullptr, Hh, Hl, DIN, Cc, 1, nullptr);
        // FFN2: F = H @ f2^T + b2 + ret(hi/lo)  (block (0,0) zeroes stats for next bn_stats)
        gemm_mma<<<dim3(Cc / 128, Pp / 128), 256, GEMM_SMEM>>>(
            Hh, Hl, f2p, f2b, reth, retl, F, nullptr, nullptr, Cc, DIN, 0, stats);

        bn_stats<<<Pp / 64, 256>>>(F, stats, Pp);

        if (ly == 0) {
            // fused BN(leaky)+LN into next layer's normalized input (no X round-trip)
            bnln_kernel<<<Pp / 8, 256>>>(F, stats, fbg, fbb,
                                         ln_g + Cc, ln_b + Cc, xn, xnh, xnl);
        } else {
            // fused BN(leaky)+transpose to output
            bnfinal_kernel<<<(TOTAL + 255) / 256, 256>>>(F, stats, fbg, fbb,
                                                         (float*)d_out);
        }
    }
}

// round 16
// speedup vs baseline: 1.0275x; 1.0275x over previous
#include <cuda_runtime.h>
#include <cuda_fp16.h>
#include <math.h>
#include <stdint.h>

// Problem constants
#define Cc 256
#define Vv 17
#define Tt 256
#define Nr 1024            // B*T
#define Pp 17408           // Nr*Vv
#define DIN 1024
#define TOTAL 4456448      // B*C*V*T
#define INV_SQRT_DK 0.17677669529663687f

// 0-indexed adjacency (padded), degrees
__constant__ int c_nbr[17][5] = {
    {0,1,2,5,6},{0,1,3,0,0},{0,2,4,0,0},{1,3,0,0,0},{2,4,0,0,0},
    {0,5,7,11,0},{0,6,8,12,0},{5,7,9,0,0},{6,8,12,0,0},{7,9,0,0,0},
    {8,10,0,0,0},{8,11,13,0,0},{10,12,14,0,0},{11,13,15,0,0},{12,14,16,0,0},
    {13,15,0,0,0},{14,16,0,0,0}
};
__constant__ int c_deg[17] = {5,3,3,2,2,4,4,3,3,2,2,3,3,3,3,2,2};

// fp32 scratch
__device__ float g_X[Pp*Cc];
__device__ float g_xn[Pp*Cc];
__device__ float g_QKV[Pp*3*Cc];
__device__ float g_AKV[Pp*2*Cc];
__device__ float g_AKVr[Nr*2*Cc];
__device__ float g_y1[Pp*Cc];
__device__ float g_F[Pp*Cc];
__device__ float g_bj[2*3*Cc];
__device__ float g_stats[2*Cc];
// fp16 hi/lo activation scratch (A operands) + fp16 weights (W operands)
__device__ __half g_Eh[Pp*Cc],  g_El[Pp*Cc];
__device__ __half g_Rh[Nr*Cc],  g_Rl[Nr*Cc];
__device__ __half g_xnh[Pp*Cc], g_xnl[Pp*Cc];
__device__ __half g_reth[Pp*Cc], g_retl[Pp*Cc];
__device__ __half g_Hh[Pp*DIN], g_Hl[Pp*DIN];
__device__ __half g_Wj[2*3*Cc*Cc];
__device__ __half g_F1[2*DIN*Cc];
__device__ __half g_F2[2*Cc*DIN];

// ---------------- helpers ----------------
__device__ __forceinline__ uint32_t smem_u32(const void* p) {
    return (uint32_t)__cvta_generic_to_shared(p);
}
__device__ __forceinline__ void cpa16(uint32_t d, const void* s) {
    asm volatile("cp.async.cg.shared.global [%0], [%1], 16;" :: "r"(d), "l"(s));
}
#define CP_COMMIT() asm volatile("cp.async.commit_group;" ::: "memory")
#define CP_WAIT1()  asm volatile("cp.async.wait_group 1;" ::: "memory")
__device__ __forceinline__ void ldsm4(uint32_t* r, uint32_t a) {
    asm volatile("ldmatrix.sync.aligned.m8n8.x4.shared.b16 {%0,%1,%2,%3}, [%4];"
                 : "=r"(r[0]), "=r"(r[1]), "=r"(r[2]), "=r"(r[3]) : "r"(a));
}
__device__ __forceinline__ void mma_f16(float* c, const uint32_t* a, const uint32_t* b) {
    asm volatile("mma.sync.aligned.m16n8k16.row.col.f32.f16.f16.f32 "
                 "{%0,%1,%2,%3}, {%4,%5,%6,%7}, {%8,%9}, {%0,%1,%2,%3};"
                 : "+f"(c[0]), "+f"(c[1]), "+f"(c[2]), "+f"(c[3])
                 : "r"(a[0]), "r"(a[1]), "r"(a[2]), "r"(a[3]), "r"(b[0]), "r"(b[1]));
}
__device__ __forceinline__ void f2hl(float v, __half& h, __half& l) {
    h = __float2half_rn(v);
    l = __float2half_rn(v - __half2float(h));
}

// ---------------- tensor-core GEMM body (mma.sync fp16x2), 3-stage ----------------
// CTA tile 64x128, warp tile 32x32 (8 warps, 2m x 4n) -> 3 CTAs/SM.
// out = A @ W^T; A[M,K] split hi/lo fp16, W[N,K] fp16, K-major.
// M%64==0, N%128==0, K%32==0. Residual (optional) given as hi/lo fp16 pair.
#define BK 32
#define TSTRIDE 80                      // padded bytes per smem row (conflict-free ldmatrix)
#define A_TILE (64*TSTRIDE)             // 5120
#define W_TILE (128*TSTRIDE)            // 10240
#define STAGE_BYTES (2*A_TILE + W_TILE) // 20480
#define NSTAGE 3
#define GEMM_SMEM (NSTAGE*STAGE_BYTES)  // 61440 -> 3 CTAs/SM

__device__ __forceinline__ void gemm_body(
    const __half* __restrict__ Ah, const __half* __restrict__ Al,
    const __half* __restrict__ W,
    const float* __restrict__ bias,
    const __half* __restrict__ resh, const __half* __restrict__ resl,
    float* __restrict__ outf, __half* __restrict__ outh, __half* __restrict__ outl,
    int N, int K, int relu, int bm, int bn, char* smem_gen)
{
    const uint32_t sb = smem_u32(smem_gen);
    const int tid = threadIdx.x;
    const int warp = tid >> 5, lane = tid & 31;
    const int wm = (warp >> 2) * 32;    // 0 or 32
    const int wn = (warp & 3) * 32;     // 0,32,64,96

    const __half* Ahp = Ah + (size_t)bm * K;
    const __half* Alp = Al + (size_t)bm * K;
    const __half* Wp  = W  + (size_t)bn * K;

    auto load_stage = [&](int stage, int kc) {
        const uint32_t base = sb + stage * STAGE_BYTES;
        const int k0 = kc * BK;
        {   // A hi / A lo: 64 rows x 4 chunks = 256 units each (1 per thread)
            int row = tid >> 2, ch = tid & 3;
            cpa16(base + row * TSTRIDE + ch * 16, Ahp + (size_t)row * K + k0 + ch * 8);
            cpa16(base + A_TILE + row * TSTRIDE + ch * 16,
                  Alp + (size_t)row * K + k0 + ch * 8);
        }
        {   // W: 128 rows x 4 chunks = 512 units (2 per thread)
            #pragma unroll
            for (int u0 = 0; u0 < 2; u0++) {
                int u = tid + u0 * 256;
                int row = u >> 2, ch = u & 3;
                cpa16(base + 2 * A_TILE + row * TSTRIDE + ch * 16,
                      Wp + (size_t)row * K + k0 + ch * 8);
            }
        }
    };

    float acc[2][4][4] = {};
    const int NCK = K / BK;

    load_stage(0, 0);
    CP_COMMIT();
    if (NCK > 1) load_stage(1, 1);
    CP_COMMIT();

    int stage = 0;
    for (int kc = 0; kc < NCK; kc++) {
        CP_WAIT1();
        __syncthreads();

        int nst = stage + 2; if (nst >= NSTAGE) nst -= NSTAGE;
        if (kc + 2 < NCK) load_stage(nst, kc + 2);
        CP_COMMIT();

        const uint32_t base = sb + stage * STAGE_BYTES;
        const uint32_t A_h = base;
        const uint32_t A_l = base + A_TILE;
        const uint32_t W_s = base + 2 * A_TILE;

        #pragma unroll
        for (int fk = 0; fk < 2; fk++) {
            uint32_t ah[2][4], al[2][4];
            {
                int arow = wm + (lane & 15);
                int abyte = fk * 32 + ((lane >> 4) << 4);
                ldsm4(ah[0], A_h + arow * TSTRIDE + abyte);
                ldsm4(ah[1], A_h + (arow + 16) * TSTRIDE + abyte);
                ldsm4(al[0], A_l + arow * TSTRIDE + abyte);
                ldsm4(al[1], A_l + (arow + 16) * TSTRIDE + abyte);
            }
            uint32_t wv[4][2];
            {
                int brow = wn + ((lane & 16) >> 1) + (lane & 7);
                int bbyte = fk * 32 + (((lane >> 3) & 1) << 4);
                #pragma unroll
                for (int fo = 0; fo < 2; fo++) {
                    uint32_t r[4];
                    ldsm4(r, W_s + (brow + fo * 16) * TSTRIDE + bbyte);
                    wv[2 * fo][0] = r[0]; wv[2 * fo][1] = r[1];
                    wv[2 * fo + 1][0] = r[2]; wv[2 * fo + 1][1] = r[3];
                }
            }
            #pragma unroll
            for (int fm = 0; fm < 2; fm++)
                #pragma unroll
                for (int fn = 0; fn < 4; fn++) {
                    mma_f16(acc[fm][fn], ah[fm], wv[fn]);   // hi*W
                    mma_f16(acc[fm][fn], al[fm], wv[fn]);   // lo*W
                }
        }
        stage++; if (stage >= NSTAGE) stage = 0;
    }

    // ---------------- epilogue ----------------
    #pragma unroll
    for (int fm = 0; fm < 2; fm++) {
        #pragma unroll
        for (int fn = 0; fn < 4; fn++) {
            int r0 = bm + wm + fm * 16 + (lane >> 2);
            int c  = bn + wn + fn * 8 + (lane & 3) * 2;
            #pragma unroll
            for (int half_ = 0; half_ < 2; half_++) {
                size_t row = (size_t)(r0 + half_ * 8);
                float v0 = acc[fm][fn][half_ * 2];
                float v1 = acc[fm][fn][half_ * 2 + 1];
                if (bias) { v0 += bias[c]; v1 += bias[c + 1]; }
                if (resh) {
                    __half2 rh = *(const __half2*)(resh + row * N + c);
                    __half2 rl = *(const __half2*)(resl + row * N + c);
                    v0 += __half2float(rh.x) + __half2float(rl.x);
                    v1 += __half2float(rh.y) + __half2float(rl.y);
                }
                if (relu) { v0 = fmaxf(v0, 0.f); v1 = fmaxf(v1, 0.f); }
                if (outf) *(float2*)(outf + row * N + c) = make_float2(v0, v1);
                if (outh) {
                    __half h0, l0, h1, l1;
                    f2hl(v0, h0, l0); f2hl(v1, h1, l1);
                    *(__half2*)(outh + row * N + c) = __halves2half2(h0, h1);
                    *(__half2*)(outl + row * N + c) = __halves2half2(l0, l1);
                }
            }
        }
    }
}

// standard GEMM kernel (FFN1 / FFN2); min 3 blocks/SM pins regs <= 85
__global__ void __launch_bounds__(256, 3) gemm_mma(
    const __half* __restrict__ Ah, const __half* __restrict__ Al,
    const __half* __restrict__ W,
    const float* __restrict__ bias,
    const __half* __restrict__ resh, const __half* __restrict__ resl,
    float* __restrict__ outf,
    __half* __restrict__ outh, __half* __restrict__ outl,
    int N, int K, int relu, float* __restrict__ zstats)
{
    extern __shared__ char smem[];
    const int bm = blockIdx.y * 64;
    const int bn = blockIdx.x * 128;
    // fold bn_zero into this launch (block (0,0); prior stats consumer already retired)
    if (zstats && bm == 0 && bn == 0) {
        zstats[threadIdx.x] = 0.f;
        zstats[256 + threadIdx.x] = 0.f;
    }
    gemm_body(Ah, Al, W, bias, resh, resl, outf, outh, outl, N, K, relu, bm, bn, smem);
}

// batched projection GEMM: QKV (1632 blocks) + AKV (1088) + AKVr (64), K=256
#define PROJ_BLOCKS (1632 + 1088 + 64)
__global__ void __launch_bounds__(256, 3) gemm_proj3(
    const __half* __restrict__ xnh, const __half* __restrict__ xnl,
    const __half* __restrict__ Eh,  const __half* __restrict__ El,
    const __half* __restrict__ Rh,  const __half* __restrict__ Rl,
    const __half* __restrict__ Wqkv, const float* __restrict__ bqkv,
    float* __restrict__ QKV, float* __restrict__ AKV, float* __restrict__ AKVr)
{
    extern __shared__ char smem[];
    int bid = blockIdx.x;
    const __half *Ah, *Al, *W;
    const float* bias;
    float* outf;
    int N, bm, bn;
    if (bid < 1632) {                  // QKV: [Pp,768] = xn @ Wqkv^T
        Ah = xnh; Al = xnl; W = Wqkv; bias = bqkv; outf = QKV; N = 768;
        bm = (bid / 6) * 64; bn = (bid % 6) * 128;
    } else if (bid < 1632 + 1088) {    // AKe|AVe: [Pp,512] = embs @ Wkv^T
        int t = bid - 1632;
        Ah = Eh; Al = El; W = Wqkv + (size_t)Cc * Cc; bias = bqkv + Cc;
        outf = AKV; N = 512;
        bm = (t / 4) * 64; bn = (t % 4) * 128;
    } else {                           // AKr|AVr: [Nr,512] = relay0 @ Wkv^T
        int t = bid - 1632 - 1088;
        Ah = Rh; Al = Rl; W = Wqkv + (size_t)Cc * Cc; bias = bqkv + Cc;
        outf = AKVr; N = 512;
        bm = (t / 4) * 64; bn = (t % 4) * 128;
    }
    gemm_body(Ah, Al, W, bias, nullptr, nullptr, outf, nullptr, nullptr, N, Cc, 0,
              bm, bn, smem);
}

// ---------------- merged layout prep + relay init (one launch) ----------------
#define PREP_TOTAL (TOTAL + Nr * Cc)
__global__ void prep_all(const float* __restrict__ data, float* __restrict__ X,
                         __half* __restrict__ Eh, __half* __restrict__ El,
                         __half* __restrict__ Rh, __half* __restrict__ Rl)
{
    int idx = blockIdx.x * blockDim.x + threadIdx.x;
    if (idx < TOTAL) {
        int t = idx % Tt;
        int v = (idx / Tt) % Vv;
        int c = (idx / (Tt * Vv)) % Cc;
        int b = idx / (Tt * Vv * Cc);
        float val = data[idx];
        size_t o = (size_t)((b * Tt + t) * Vv + v) * Cc + c;
        X[o] = val;
        f2hl(val, Eh[o], El[o]);
    } else if (idx < PREP_TOTAL) {
        int j = idx - TOTAL;
        int n = j >> 8;
        int c = j & 255;
        int b = n / Tt, t = n - b * Tt;
        float s = 0.f;
        #pragma unroll
        for (int v = 0; v < Vv; v++)
            s += data[(size_t)((b * Cc + c) * Vv + v) * Tt + t];
        f2hl(s * (1.0f / Vv), Rh[j], Rl[j]);
    }
}

// ---------------- merged weight prep (both layers, one launch) ----------------
#define WPREP_TOTAL 720896
__global__ void wprep2(const float* __restrict__ jq, const float* __restrict__ jk,
                       const float* __restrict__ jv,
                       const float* __restrict__ jqb, const float* __restrict__ jkb,
                       const float* __restrict__ jvb,
                       const float* __restrict__ jf1, const float* __restrict__ jf2,
                       __half* __restrict__ Wp, float* __restrict__ b,
                       __half* __restrict__ F1p, __half* __restrict__ F2p)
{
    int gidx = blockIdx.x * blockDim.x + threadIdx.x;
    if (gidx >= 2 * WPREP_TOTAL) return;
    int ly = gidx >= WPREP_TOTAL;
    int idx = gidx - ly * WPREP_TOTAL;
    const float* q  = jq + (size_t)ly * Cc * Cc;
    const float* k  = jk + (size_t)ly * Cc * Cc;
    const float* v  = jv + (size_t)ly * Cc * Cc;
    const float* f1 = jf1 + (size_t)ly * DIN * Cc;
    const float* f2 = jf2 + (size_t)ly * Cc * DIN;
    __half* Wl  = Wp + (size_t)ly * 3 * Cc * Cc;
    __half* F1l = F1p + (size_t)ly * DIN * Cc;
    __half* F2l = F2p + (size_t)ly * Cc * DIN;
    float* bl   = b + (size_t)ly * 3 * Cc;
    if (idx < 3 * Cc) {
        const float* qb = jqb + ly * Cc;
        const float* kb = jkb + ly * Cc;
        const float* vb = jvb + ly * Cc;
        bl[idx] = (idx < Cc) ? qb[idx] : (idx < 2 * Cc) ? kb[idx - Cc] : vb[idx - 2 * Cc];
    }
    if (idx < 3 * Cc * Cc) {
        int row = idx >> 8;
        int col = idx & 255;
        const float* src = (row < Cc) ? q + (size_t)row * Cc
                         : (row < 2 * Cc) ? k + (size_t)(row - Cc) * Cc
                         : v + (size_t)(row - 2 * Cc) * Cc;
        Wl[idx] = __float2half_rn(src[col]);
    } else if (idx < 3 * Cc * Cc + DIN * Cc) {
        int i = idx - 3 * Cc * Cc;
        F1l[i] = __float2half_rn(f1[i]);
    } else {
        int i = idx - 3 * Cc * Cc - DIN * Cc;
        F2l[i] = __float2half_rn(f2[i]);
    }
}

// ---------------- LayerNorm (layer-0 entry: reads X) ----------------
__global__ void __launch_bounds__(256) ln_kernel(const float* __restrict__ x,
                                                 const float* __restrict__ g,
                                                 const float* __restrict__ b,
                                                 float* __restrict__ y,
                                                 __half* __restrict__ yh,
                                                 __half* __restrict__ yl)
{
    int row = blockIdx.x * 8 + (threadIdx.x >> 5);
    int lane = threadIdx.x & 31;
    const float* xr = x + (size_t)row * Cc;
    float v[8];
    float s = 0.f;
    #pragma unroll
    for (int i = 0; i < 8; i++) { v[i] = xr[lane + 32 * i]; s += v[i]; }
    #pragma unroll
    for (int o = 16; o; o >>= 1) s += __shfl_xor_sync(~0u, s, o);
    float mean = s * (1.0f / Cc);
    float s2 = 0.f;
    #pragma unroll
    for (int i = 0; i < 8; i++) { float d = v[i] - mean; s2 += d * d; }
    #pragma unroll
    for (int o = 16; o; o >>= 1) s2 += __shfl_xor_sync(~0u, s2, o);
    float rs = rsqrtf(s2 * (1.0f / Cc) + 1e-6f);
    #pragma unroll
    for (int i = 0; i < 8; i++) {
        int c = lane + 32 * i;
        size_t o = (size_t)row * Cc + c;
        float yv = (v[i] - mean) * rs * g[c] + b[c];
        y[o] = yv;
        f2hl(yv, yh[o], yl[o]);
    }
}

// ---------------- fused BN(leaky) + LN  (layer boundary; skips X round-trip) --------
__global__ void __launch_bounds__(256) bnln_kernel(const float* __restrict__ F,
                                                   const float* __restrict__ stats,
                                                   const float* __restrict__ fg,
                                                   const float* __restrict__ fb,
                                                   const float* __restrict__ lg,
                                                   const float* __restrict__ lb,
                                                   float* __restrict__ y,
                                                   __half* __restrict__ yh,
                                                   __half* __restrict__ yl)
{
    int row = blockIdx.x * 8 + (threadIdx.x >> 5);
    int lane = threadIdx.x & 31;
    const float* xr = F + (size_t)row * Cc;
    const float inv = 1.0f / Pp;
    float v[8];
    float s = 0.f;
    #pragma unroll
    for (int i = 0; i < 8; i++) {
        int c = lane + 32 * i;
        float mean = stats[c] * inv;
        float var = stats[Cc + c] * inv - mean * mean;
        float t = (xr[c] - mean) * rsqrtf(var + 1e-5f) * fg[c] + fb[c];
        t = t > 0.f ? t : 0.01f * t;          // leaky
        v[i] = t;
        s += t;
    }
    #pragma unroll
    for (int o = 16; o; o >>= 1) s += __shfl_xor_sync(~0u, s, o);
    float mean = s * (1.0f / Cc);
    float s2 = 0.f;
    #pragma unroll
    for (int i = 0; i < 8; i++) { float d = v[i] - mean; s2 += d * d; }
    #pragma unroll
    for (int o = 16; o; o >>= 1) s2 += __shfl_xor_sync(~0u, s2, o);
    float rs = rsqrtf(s2 * (1.0f / Cc) + 1e-6f);
    #pragma unroll
    for (int i = 0; i < 8; i++) {
        int c = lane + 32 * i;
        size_t o = (size_t)row * Cc + c;
        float yv = (v[i] - mean) * rs * lg[c] + lb[c];
        y[o] = yv;
        f2hl(yv, yh[o], yl[o]);
    }
}

// ---------------- fused BN(leaky) + output transpose (final layer) ----------------
__global__ void __launch_bounds__(256) bnfinal_kernel(const float* __restrict__ F,
                                                      const float* __restrict__ stats,
                                                      const float* __restrict__ g,
                                                      const float* __restrict__ b,
                                                      float* __restrict__ out)
{
    int idx = blockIdx.x * blockDim.x + threadIdx.x;
    if (idx >= TOTAL) return;
    int t = idx % Tt;
    int v = (idx / Tt) % Vv;
    int c = (idx / (Tt * Vv)) % Cc;
    int bb = idx / (Tt * Vv * Cc);
    float f = F[(size_t)((bb * Tt + t) * Vv + v) * Cc + c];
    const float inv = 1.0f / Pp;
    float mean = stats[c] * inv;
    float var = stats[Cc + c] * inv - mean * mean;
    float val = (f - mean) * rsqrtf(var + 1e-5f) * g[c] + b[c];
    out[idx] = val > 0.f ? val : 0.01f * val;
}

// ---------------- graph attention (7 slots), packed inputs ----------------
__global__ void __launch_bounds__(256) attn_j(const float* __restrict__ QKV,
                                              const float* __restrict__ AKV,
                                              const float* __restrict__ AKVr,
                                              const float* __restrict__ xn,
                                              float* __restrict__ y1,
                                              float* __restrict__ zstats)
{
    int p = blockIdx.x;
    int co = threadIdx.x;
    if (p == 0) { zstats[co] = 0.f; zstats[256 + co] = 0.f; }   // fold bn_zero
    int n = p / Vv, l = p - n * Vv;
    size_t qbase = (size_t)p * 768 + co;
    size_t abase = (size_t)p * 512 + co;
    size_t rbase = (size_t)n * 512 + co;
    float q = QKV[qbase];
    int deg = c_deg[l];
    float sc[7];
    #pragma unroll
    for (int w = 0; w < 5; w++) {
        float d = -1e30f;
        if (w < deg) {
            int j = c_nbr[l][w];
            float dd = q * QKV[(size_t)(n * Vv + j) * 768 + 256 + co];
            #pragma unroll
            for (int o = 16; o; o >>= 1) dd += __shfl_xor_sync(~0u, dd, o);
            d = dd * INV_SQRT_DK;
        }
        sc[w] = d;
    }
    {
        float dd = q * AKV[abase];
        #pragma unroll
        for (int o = 16; o; o >>= 1) dd += __shfl_xor_sync(~0u, dd, o);
        sc[5] = dd * INV_SQRT_DK;
        dd = q * AKVr[rbase];
        #pragma unroll
        for (int o = 16; o; o >>= 1) dd += __shfl_xor_sync(~0u, dd, o);
        sc[6] = dd * INV_SQRT_DK;
    }
    float mx = sc[0];
    #pragma unroll
    for (int w = 1; w < 7; w++) mx = fmaxf(mx, sc[w]);
    float wg[7];
    float sum = 0.f;
    #pragma unroll
    for (int w = 0; w < 7; w++) { wg[w] = expf(sc[w] - mx); sum += wg[w]; }
    float att = 0.f;
    #pragma unroll
    for (int w = 0; w < 5; w++)
        if (w < deg) att += wg[w] * QKV[(size_t)(n * Vv + c_nbr[l][w]) * 768 + 512 + co];
    att += wg[5] * AKV[abase + 256] + wg[6] * AKVr[rbase + 256];
    y1[(size_t)p * Cc + co] = xn[(size_t)p * Cc + co] + att / sum;
}

// ---------------- BatchNorm (axes 0,2) ----------------
__global__ void __launch_bounds__(256) bn_stats(const float* __restrict__ x,
                                                float* __restrict__ stats, int rows)
{
    int c = threadIdx.x;
    int r0 = blockIdx.x * 64;
    float s = 0.f, s2 = 0.f;
    for (int r = r0; r < r0 + 64; r++) {
        float v = x[(size_t)r * Cc + c];
        s += v; s2 += v * v;
    }
    atomicAdd(&stats[c], s);
    atomicAdd(&stats[Cc + c], s2);
}

__global__ void __launch_bounds__(256) bn_apply(const float* __restrict__ x,
                                                const float* __restrict__ stats,
                                                const float* __restrict__ g,
                                                const float* __restrict__ b,
                                                __half* __restrict__ yh,
                                                __half* __restrict__ yl,
                                                int rows, int leaky)
{
    int idx = blockIdx.x * blockDim.x + threadIdx.x;
    if (idx >= rows * Cc) return;
    int c = idx & 255;
    float inv = 1.0f / rows;
    float mean = stats[c] * inv;
    float var = stats[Cc + c] * inv - mean * mean;
    float v = (x[idx] - mean) * rsqrtf(var + 1e-5f) * g[c] + b[c];
    if (leaky) v = v > 0.f ? v : 0.01f * v;
    f2hl(v, yh[idx], yl[idx]);
}

// ---------------- host ----------------
template <typename Sym>
static float* sym_f(const Sym& s) { void* p = nullptr; cudaGetSymbolAddress(&p, s); return (float*)p; }
template <typename Sym>
static __half* sym_h(const Sym& s) { void* p = nullptr; cudaGetSymbolAddress(&p, s); return (__half*)p; }

extern "C" void kernel_launch(void* const* d_in, const int* in_sizes, int n_in,
                              void* d_out, int out_size)
{
    const float* data  = (const float*)d_in[0];
    const float* ln_g  = (const float*)d_in[1];
    const float* ln_b  = (const float*)d_in[2];
    const float* jq_w  = (const float*)d_in[3];
    const float* jq_b  = (const float*)d_in[4];
    const float* jk_w  = (const float*)d_in[5];
    const float* jk_b  = (const float*)d_in[6];
    const float* jv_w  = (const float*)d_in[7];
    const float* jv_b  = (const float*)d_in[8];
    const float* jbn_g = (const float*)d_in[9];
    const float* jbn_b = (const float*)d_in[10];
    const float* jf1_w = (const float*)d_in[11];
    const float* jf1_b = (const float*)d_in[12];
    const float* jf2_w = (const float*)d_in[13];
    const float* jf2_b = (const float*)d_in[14];
    const float* jfbn_g = (const float*)d_in[15];
    const float* jfbn_b = (const float*)d_in[16];
    // relay-path weights (d_in[17..30]) are dead: relay never feeds back into nodes.

    float* X    = sym_f(g_X);
    float* xn   = sym_f(g_xn);
    float* QKV  = sym_f(g_QKV);
    float* AKV  = sym_f(g_AKV);
    float* AKVr = sym_f(g_AKVr);
    float* y1   = sym_f(g_y1);
    float* F    = sym_f(g_F);
    float* bj   = sym_f(g_bj);
    float* stats = sym_f(g_stats);
    __half *Eh = sym_h(g_Eh), *El = sym_h(g_El);
    __half *Rh = sym_h(g_Rh), *Rl = sym_h(g_Rl);
    __half *xnh = sym_h(g_xnh), *xnl = sym_h(g_xnl);
    __half *reth = sym_h(g_reth), *retl = sym_h(g_retl);
    __half *Hh = sym_h(g_Hh), *Hl = sym_h(g_Hl);
    __half *Wj = sym_h(g_Wj);
    __half *F1 = sym_h(g_F1);
    __half *F2 = sym_h(g_F2);

    static bool attr_set = false;
    if (!attr_set) {
        cudaFuncSetAttribute(gemm_mma, cudaFuncAttributeMaxDynamicSharedMemorySize, GEMM_SMEM);
        cudaFuncSetAttribute(gemm_proj3, cudaFuncAttributeMaxDynamicSharedMemorySize, GEMM_SMEM);
        attr_set = true;
    }

    // merged transpose + relay init (launch 0)
    prep_all<<<(PREP_TOTAL + 255) / 256, 256>>>(data, X, Eh, El, Rh, Rl);

    wprep2<<<(2 * WPREP_TOTAL + 255) / 256, 256>>>(
        jq_w, jk_w, jv_w, jq_b, jk_b, jv_b, jf1_w, jf2_w,
        Wj, bj, F1, F2);

    // layer-0 entry LN reads X
    ln_kernel<<<Pp / 8, 256>>>(X, ln_g, ln_b, xn, xnh, xnl);

    for (int ly = 0; ly < 2; ly++) {
        const __half* Wl = Wj + (size_t)ly * 3 * Cc * Cc;
        const float* bl  = bj + (size_t)ly * 3 * Cc;
        const float* bng = jbn_g + ly * Cc;
        const float* bnb = jbn_b + ly * Cc;
        const __half* f1p = F1 + (size_t)ly * DIN * Cc;
        const float* f1b = jf1_b + ly * DIN;
        const __half* f2p = F2 + (size_t)ly * Cc * DIN;
        const float* f2b = jf2_b + ly * Cc;
        const float* fbg = jfbn_g + ly * Cc;
        const float* fbb = jfbn_b + ly * Cc;

        // all three projections in ONE launch (QKV | AKV | AKVr)
        gemm_proj3<<<PROJ_BLOCKS, 256, GEMM_SMEM>>>(
            xnh, xnl, Eh, El, Rh, Rl, Wl, bl, QKV, AKV, AKVr);

        attn_j<<<Pp, 256>>>(QKV, AKV, AKVr, xn, y1, stats);   // zeroes stats (block 0)

        bn_stats<<<Pp / 64, 256>>>(y1, stats, Pp);
        bn_apply<<<(Pp * Cc + 255) / 256, 256>>>(y1, stats, bng, bnb, reth, retl, Pp, 0);

        // FFN1: H = relu(ret @ f1^T + b1), written directly as hi/lo fp16
        gemm_mma<<<dim3(DIN / 128, Pp / 64), 256, GEMM_SMEM>>>(
            reth, retl, f1p, f1b, nullptr, nullptr, nullptr, Hh, Hl, DIN, Cc, 1, nullptr);
        // FFN2: F = H @ f2^T + b2 + ret(hi/lo)  (block (0,0) zeroes stats for next bn_stats)
        gemm_mma<<<dim3(Cc / 128, Pp / 64), 256, GEMM_SMEM>>>(
            Hh, Hl, f2p, f2b, reth, retl, F, nullptr, nullptr, Cc, DIN, 0, stats);

        bn_stats<<<Pp / 64, 256>>>(F, stats, Pp);

        if (ly == 0) {
            // fused BN(leaky)+LN into next layer's normalized input (no X round-trip)
            bnln_kernel<<<Pp / 8, 256>>>(F, stats, fbg, fbb,
                                         ln_g + Cc, ln_b + Cc, xn, xnh, xnl);
        } else {
            // fused BN(leaky)+transpose to output
            bnfinal_kernel<<<(TOTAL + 255) / 256, 256>>>(F, stats, fbg, fbb,
                                                         (float*)d_out);
        }
    }
}

// round 17
// speedup vs baseline: 1.0434x; 1.0155x over previous
#include <cuda_runtime.h>
#include <cuda_fp16.h>
#include <math.h>
#include <stdint.h>

// Problem constants
#define Cc 256
#define Vv 17
#define Tt 256
#define Nr 1024            // B*T
#define Pp 17408           // Nr*Vv
#define DIN 1024
#define TOTAL 4456448      // B*C*V*T
#define INV_SQRT_DK 0.17677669529663687f

// 0-indexed adjacency (padded), degrees
__constant__ int c_nbr[17][5] = {
    {0,1,2,5,6},{0,1,3,0,0},{0,2,4,0,0},{1,3,0,0,0},{2,4,0,0,0},
    {0,5,7,11,0},{0,6,8,12,0},{5,7,9,0,0},{6,8,12,0,0},{7,9,0,0,0},
    {8,10,0,0,0},{8,11,13,0,0},{10,12,14,0,0},{11,13,15,0,0},{12,14,16,0,0},
    {13,15,0,0,0},{14,16,0,0,0}
};
__constant__ int c_deg[17] = {5,3,3,2,2,4,4,3,3,2,2,3,3,3,3,2,2};

// fp32 scratch
__device__ float g_X[Pp*Cc];
__device__ float g_QKV[Pp*3*Cc];
__device__ float g_AKV[Pp*2*Cc];
__device__ float g_AKVr[Nr*2*Cc];
__device__ float g_y1[Pp*Cc];
__device__ float g_F[Pp*Cc];
__device__ float g_bj[2*3*Cc];
__device__ float g_stats[2*Cc];
// fp16 hi/lo activation scratch (A operands) + fp16 weights (W operands)
__device__ __half g_Eh[Pp*Cc],  g_El[Pp*Cc];
__device__ __half g_Rh[Nr*Cc],  g_Rl[Nr*Cc];
__device__ __half g_xnh[Pp*Cc], g_xnl[Pp*Cc];
__device__ __half g_reth[Pp*Cc], g_retl[Pp*Cc];
__device__ __half g_Hh[Pp*DIN], g_Hl[Pp*DIN];
__device__ __half g_Wj[2*3*Cc*Cc];
__device__ __half g_F1[2*DIN*Cc];
__device__ __half g_F2[2*Cc*DIN];

// ---------------- helpers ----------------
__device__ __forceinline__ uint32_t smem_u32(const void* p) {
    return (uint32_t)__cvta_generic_to_shared(p);
}
__device__ __forceinline__ void cpa16(uint32_t d, const void* s) {
    asm volatile("cp.async.cg.shared.global [%0], [%1], 16;" :: "r"(d), "l"(s));
}
#define CP_COMMIT() asm volatile("cp.async.commit_group;" ::: "memory")
#define CP_WAIT1()  asm volatile("cp.async.wait_group 1;" ::: "memory")
__device__ __forceinline__ void ldsm4(uint32_t* r, uint32_t a) {
    asm volatile("ldmatrix.sync.aligned.m8n8.x4.shared.b16 {%0,%1,%2,%3}, [%4];"
                 : "=r"(r[0]), "=r"(r[1]), "=r"(r[2]), "=r"(r[3]) : "r"(a));
}
__device__ __forceinline__ void mma_f16(float* c, const uint32_t* a, const uint32_t* b) {
    asm volatile("mma.sync.aligned.m16n8k16.row.col.f32.f16.f16.f32 "
                 "{%0,%1,%2,%3}, {%4,%5,%6,%7}, {%8,%9}, {%0,%1,%2,%3};"
                 : "+f"(c[0]), "+f"(c[1]), "+f"(c[2]), "+f"(c[3])
                 : "r"(a[0]), "r"(a[1]), "r"(a[2]), "r"(a[3]), "r"(b[0]), "r"(b[1]));
}
__device__ __forceinline__ void f2hl(float v, __half& h, __half& l) {
    h = __float2half_rn(v);
    l = __float2half_rn(v - __half2float(h));
}

// ---------------- tensor-core GEMM body (mma.sync fp16x2), 3-stage ----------------
// CTA tile 64x128, warp tile 32x32 (8 warps, 2m x 4n) -> 3 CTAs/SM.
// out = A @ W^T; A[M,K] split hi/lo fp16, W[N,K] fp16, K-major.
// M%64==0, N%128==0, K%32==0. Residual (optional) given as hi/lo fp16 pair.
#define BK 32
#define TSTRIDE 80                      // padded bytes per smem row (conflict-free ldmatrix)
#define A_TILE (64*TSTRIDE)             // 5120
#define W_TILE (128*TSTRIDE)            // 10240
#define STAGE_BYTES (2*A_TILE + W_TILE) // 20480
#define NSTAGE 3
#define GEMM_SMEM (NSTAGE*STAGE_BYTES)  // 61440 -> 3 CTAs/SM

__device__ __forceinline__ void gemm_body(
    const __half* __restrict__ Ah, const __half* __restrict__ Al,
    const __half* __restrict__ W,
    const float* __restrict__ bias,
    const __half* __restrict__ resh, const __half* __restrict__ resl,
    float* __restrict__ outf, __half* __restrict__ outh, __half* __restrict__ outl,
    int N, int K, int relu, int bm, int bn, char* smem_gen)
{
    const uint32_t sb = smem_u32(smem_gen);
    const int tid = threadIdx.x;
    const int warp = tid >> 5, lane = tid & 31;
    const int wm = (warp >> 2) * 32;    // 0 or 32
    const int wn = (warp & 3) * 32;     // 0,32,64,96

    const __half* Ahp = Ah + (size_t)bm * K;
    const __half* Alp = Al + (size_t)bm * K;
    const __half* Wp  = W  + (size_t)bn * K;

    auto load_stage = [&](int stage, int kc) {
        const uint32_t base = sb + stage * STAGE_BYTES;
        const int k0 = kc * BK;
        {   // A hi / A lo: 64 rows x 4 chunks = 256 units each (1 per thread)
            int row = tid >> 2, ch = tid & 3;
            cpa16(base + row * TSTRIDE + ch * 16, Ahp + (size_t)row * K + k0 + ch * 8);
            cpa16(base + A_TILE + row * TSTRIDE + ch * 16,
                  Alp + (size_t)row * K + k0 + ch * 8);
        }
        {   // W: 128 rows x 4 chunks = 512 units (2 per thread)
            #pragma unroll
            for (int u0 = 0; u0 < 2; u0++) {
                int u = tid + u0 * 256;
                int row = u >> 2, ch = u & 3;
                cpa16(base + 2 * A_TILE + row * TSTRIDE + ch * 16,
                      Wp + (size_t)row * K + k0 + ch * 8);
            }
        }
    };

    float acc[2][4][4] = {};
    const int NCK = K / BK;

    load_stage(0, 0);
    CP_COMMIT();
    if (NCK > 1) load_stage(1, 1);
    CP_COMMIT();

    int stage = 0;
    for (int kc = 0; kc < NCK; kc++) {
        CP_WAIT1();
        __syncthreads();

        int nst = stage + 2; if (nst >= NSTAGE) nst -= NSTAGE;
        if (kc + 2 < NCK) load_stage(nst, kc + 2);
        CP_COMMIT();

        const uint32_t base = sb + stage * STAGE_BYTES;
        const uint32_t A_h = base;
        const uint32_t A_l = base + A_TILE;
        const uint32_t W_s = base + 2 * A_TILE;

        #pragma unroll
        for (int fk = 0; fk < 2; fk++) {
            uint32_t ah[2][4], al[2][4];
            {
                int arow = wm + (lane & 15);
                int abyte = fk * 32 + ((lane >> 4) << 4);
                ldsm4(ah[0], A_h + arow * TSTRIDE + abyte);
                ldsm4(ah[1], A_h + (arow + 16) * TSTRIDE + abyte);
                ldsm4(al[0], A_l + arow * TSTRIDE + abyte);
                ldsm4(al[1], A_l + (arow + 16) * TSTRIDE + abyte);
            }
            uint32_t wv[4][2];
            {
                int brow = wn + ((lane & 16) >> 1) + (lane & 7);
                int bbyte = fk * 32 + (((lane >> 3) & 1) << 4);
                #pragma unroll
                for (int fo = 0; fo < 2; fo++) {
                    uint32_t r[4];
                    ldsm4(r, W_s + (brow + fo * 16) * TSTRIDE + bbyte);
                    wv[2 * fo][0] = r[0]; wv[2 * fo][1] = r[1];
                    wv[2 * fo + 1][0] = r[2]; wv[2 * fo + 1][1] = r[3];
                }
            }
            #pragma unroll
            for (int fm = 0; fm < 2; fm++)
                #pragma unroll
                for (int fn = 0; fn < 4; fn++) {
                    mma_f16(acc[fm][fn], ah[fm], wv[fn]);   // hi*W
                    mma_f16(acc[fm][fn], al[fm], wv[fn]);   // lo*W
                }
        }
        stage++; if (stage >= NSTAGE) stage = 0;
    }

    // ---------------- epilogue ----------------
    #pragma unroll
    for (int fm = 0; fm < 2; fm++) {
        #pragma unroll
        for (int fn = 0; fn < 4; fn++) {
            int r0 = bm + wm + fm * 16 + (lane >> 2);
            int c  = bn + wn + fn * 8 + (lane & 3) * 2;
            #pragma unroll
            for (int half_ = 0; half_ < 2; half_++) {
                size_t row = (size_t)(r0 + half_ * 8);
                float v0 = acc[fm][fn][half_ * 2];
                float v1 = acc[fm][fn][half_ * 2 + 1];
                if (bias) { v0 += bias[c]; v1 += bias[c + 1]; }
                if (resh) {
                    __half2 rh = *(const __half2*)(resh + row * N + c);
                    __half2 rl = *(const __half2*)(resl + row * N + c);
                    v0 += __half2float(rh.x) + __half2float(rl.x);
                    v1 += __half2float(rh.y) + __half2float(rl.y);
                }
                if (relu) { v0 = fmaxf(v0, 0.f); v1 = fmaxf(v1, 0.f); }
                if (outf) *(float2*)(outf + row * N + c) = make_float2(v0, v1);
                if (outh) {
                    __half h0, l0, h1, l1;
                    f2hl(v0, h0, l0); f2hl(v1, h1, l1);
                    *(__half2*)(outh + row * N + c) = __halves2half2(h0, h1);
                    *(__half2*)(outl + row * N + c) = __halves2half2(l0, l1);
                }
            }
        }
    }
}

// standard GEMM kernel (FFN1 / FFN2); min 3 blocks/SM pins regs <= 85
__global__ void __launch_bounds__(256, 3) gemm_mma(
    const __half* __restrict__ Ah, const __half* __restrict__ Al,
    const __half* __restrict__ W,
    const float* __restrict__ bias,
    const __half* __restrict__ resh, const __half* __restrict__ resl,
    float* __restrict__ outf,
    __half* __restrict__ outh, __half* __restrict__ outl,
    int N, int K, int relu, float* __restrict__ zstats)
{
    extern __shared__ char smem[];
    const int bm = blockIdx.y * 64;
    const int bn = blockIdx.x * 128;
    // fold bn_zero into this launch (block (0,0); prior stats consumer already retired)
    if (zstats && bm == 0 && bn == 0) {
        zstats[threadIdx.x] = 0.f;
        zstats[256 + threadIdx.x] = 0.f;
    }
    gemm_body(Ah, Al, W, bias, resh, resl, outf, outh, outl, N, K, relu, bm, bn, smem);
}

// batched projection GEMM: QKV (1632 blocks) + AKV (1088) + AKVr (64), K=256
#define PROJ_BLOCKS (1632 + 1088 + 64)
__global__ void __launch_bounds__(256, 3) gemm_proj3(
    const __half* __restrict__ xnh, const __half* __restrict__ xnl,
    const __half* __restrict__ Eh,  const __half* __restrict__ El,
    const __half* __restrict__ Rh,  const __half* __restrict__ Rl,
    const __half* __restrict__ Wqkv, const float* __restrict__ bqkv,
    float* __restrict__ QKV, float* __restrict__ AKV, float* __restrict__ AKVr)
{
    extern __shared__ char smem[];
    int bid = blockIdx.x;
    const __half *Ah, *Al, *W;
    const float* bias;
    float* outf;
    int N, bm, bn;
    if (bid < 1632) {                  // QKV: [Pp,768] = xn @ Wqkv^T
        Ah = xnh; Al = xnl; W = Wqkv; bias = bqkv; outf = QKV; N = 768;
        bm = (bid / 6) * 64; bn = (bid % 6) * 128;
    } else if (bid < 1632 + 1088) {    // AKe|AVe: [Pp,512] = embs @ Wkv^T
        int t = bid - 1632;
        Ah = Eh; Al = El; W = Wqkv + (size_t)Cc * Cc; bias = bqkv + Cc;
        outf = AKV; N = 512;
        bm = (t / 4) * 64; bn = (t % 4) * 128;
    } else {                           // AKr|AVr: [Nr,512] = relay0 @ Wkv^T
        int t = bid - 1632 - 1088;
        Ah = Rh; Al = Rl; W = Wqkv + (size_t)Cc * Cc; bias = bqkv + Cc;
        outf = AKVr; N = 512;
        bm = (t / 4) * 64; bn = (t % 4) * 128;
    }
    gemm_body(Ah, Al, W, bias, nullptr, nullptr, outf, nullptr, nullptr, N, Cc, 0,
              bm, bn, smem);
}

// ---------------- layout / prep (split form: coalesced relay from X) ----------------
__global__ void prep_kernel(const float* __restrict__ data, float* __restrict__ X,
                            __half* __restrict__ Eh, __half* __restrict__ El)
{
    int idx = blockIdx.x * blockDim.x + threadIdx.x;
    if (idx >= TOTAL) return;
    int t = idx % Tt;
    int v = (idx / Tt) % Vv;
    int c = (idx / (Tt * Vv)) % Cc;
    int b = idx / (Tt * Vv * Cc);
    float val = data[idx];
    size_t o = (size_t)((b * Tt + t) * Vv + v) * Cc + c;
    X[o] = val;
    f2hl(val, Eh[o], El[o]);
}

__global__ void relay_init_kernel(const float* __restrict__ X,
                                  __half* __restrict__ Rh, __half* __restrict__ Rl)
{
    int idx = blockIdx.x * blockDim.x + threadIdx.x;
    if (idx >= Nr * Cc) return;
    int n = idx >> 8;
    int c = idx & 255;
    float s = 0.f;
    #pragma unroll
    for (int v = 0; v < Vv; v++) s += X[(size_t)(n * Vv + v) * Cc + c];
    f2hl(s * (1.0f / Vv), Rh[idx], Rl[idx]);
}

// ---------------- merged weight prep (both layers, one launch) ----------------
#define WPREP_TOTAL 720896
__global__ void wprep2(const float* __restrict__ jq, const float* __restrict__ jk,
                       const float* __restrict__ jv,
                       const float* __restrict__ jqb, const float* __restrict__ jkb,
                       const float* __restrict__ jvb,
                       const float* __restrict__ jf1, const float* __restrict__ jf2,
                       __half* __restrict__ Wp, float* __restrict__ b,
                       __half* __restrict__ F1p, __half* __restrict__ F2p)
{
    int gidx = blockIdx.x * blockDim.x + threadIdx.x;
    if (gidx >= 2 * WPREP_TOTAL) return;
    int ly = gidx >= WPREP_TOTAL;
    int idx = gidx - ly * WPREP_TOTAL;
    const float* q  = jq + (size_t)ly * Cc * Cc;
    const float* k  = jk + (size_t)ly * Cc * Cc;
    const float* v  = jv + (size_t)ly * Cc * Cc;
    const float* f1 = jf1 + (size_t)ly * DIN * Cc;
    const float* f2 = jf2 + (size_t)ly * Cc * DIN;
    __half* Wl  = Wp + (size_t)ly * 3 * Cc * Cc;
    __half* F1l = F1p + (size_t)ly * DIN * Cc;
    __half* F2l = F2p + (size_t)ly * Cc * DIN;
    float* bl   = b + (size_t)ly * 3 * Cc;
    if (idx < 3 * Cc) {
        const float* qb = jqb + ly * Cc;
        const float* kb = jkb + ly * Cc;
        const float* vb = jvb + ly * Cc;
        bl[idx] = (idx < Cc) ? qb[idx] : (idx < 2 * Cc) ? kb[idx - Cc] : vb[idx - 2 * Cc];
    }
    if (idx < 3 * Cc * Cc) {
        int row = idx >> 8;
        int col = idx & 255;
        const float* src = (row < Cc) ? q + (size_t)row * Cc
                         : (row < 2 * Cc) ? k + (size_t)(row - Cc) * Cc
                         : v + (size_t)(row - 2 * Cc) * Cc;
        Wl[idx] = __float2half_rn(src[col]);
    } else if (idx < 3 * Cc * Cc + DIN * Cc) {
        int i = idx - 3 * Cc * Cc;
        F1l[i] = __float2half_rn(f1[i]);
    } else {
        int i = idx - 3 * Cc * Cc - DIN * Cc;
        F2l[i] = __float2half_rn(f2[i]);
    }
}

// ---------------- LayerNorm (layer-0 entry: reads X, emits hi/lo only) ------------
__global__ void __launch_bounds__(256) ln_kernel(const float* __restrict__ x,
                                                 const float* __restrict__ g,
                                                 const float* __restrict__ b,
                                                 __half* __restrict__ yh,
                                                 __half* __restrict__ yl)
{
    int row = blockIdx.x * 8 + (threadIdx.x >> 5);
    int lane = threadIdx.x & 31;
    const float* xr = x + (size_t)row * Cc;
    float v[8];
    float s = 0.f;
    #pragma unroll
    for (int i = 0; i < 8; i++) { v[i] = xr[lane + 32 * i]; s += v[i]; }
    #pragma unroll
    for (int o = 16; o; o >>= 1) s += __shfl_xor_sync(~0u, s, o);
    float mean = s * (1.0f / Cc);
    float s2 = 0.f;
    #pragma unroll
    for (int i = 0; i < 8; i++) { float d = v[i] - mean; s2 += d * d; }
    #pragma unroll
    for (int o = 16; o; o >>= 1) s2 += __shfl_xor_sync(~0u, s2, o);
    float rs = rsqrtf(s2 * (1.0f / Cc) + 1e-6f);
    #pragma unroll
    for (int i = 0; i < 8; i++) {
        int c = lane + 32 * i;
        size_t o = (size_t)row * Cc + c;
        float yv = (v[i] - mean) * rs * g[c] + b[c];
        f2hl(yv, yh[o], yl[o]);
    }
}

// ---------------- fused BN(leaky) + LN  (layer boundary; hi/lo output only) --------
__global__ void __launch_bounds__(256) bnln_kernel(const float* __restrict__ F,
                                                   const float* __restrict__ stats,
                                                   const float* __restrict__ fg,
                                                   const float* __restrict__ fb,
                                                   const float* __restrict__ lg,
                                                   const float* __restrict__ lb,
                                                   __half* __restrict__ yh,
                                                   __half* __restrict__ yl)
{
    int row = blockIdx.x * 8 + (threadIdx.x >> 5);
    int lane = threadIdx.x & 31;
    const float* xr = F + (size_t)row * Cc;
    const float inv = 1.0f / Pp;
    float v[8];
    float s = 0.f;
    #pragma unroll
    for (int i = 0; i < 8; i++) {
        int c = lane + 32 * i;
        float mean = stats[c] * inv;
        float var = stats[Cc + c] * inv - mean * mean;
        float t = (xr[c] - mean) * rsqrtf(var + 1e-5f) * fg[c] + fb[c];
        t = t > 0.f ? t : 0.01f * t;          // leaky
        v[i] = t;
        s += t;
    }
    #pragma unroll
    for (int o = 16; o; o >>= 1) s += __shfl_xor_sync(~0u, s, o);
    float mean = s * (1.0f / Cc);
    float s2 = 0.f;
    #pragma unroll
    for (int i = 0; i < 8; i++) { float d = v[i] - mean; s2 += d * d; }
    #pragma unroll
    for (int o = 16; o; o >>= 1) s2 += __shfl_xor_sync(~0u, s2, o);
    float rs = rsqrtf(s2 * (1.0f / Cc) + 1e-6f);
    #pragma unroll
    for (int i = 0; i < 8; i++) {
        int c = lane + 32 * i;
        size_t o = (size_t)row * Cc + c;
        float yv = (v[i] - mean) * rs * lg[c] + lb[c];
        f2hl(yv, yh[o], yl[o]);
    }
}

// ---------------- fused BN(leaky) + output transpose (final layer) ----------------
__global__ void __launch_bounds__(256) bnfinal_kernel(const float* __restrict__ F,
                                                      const float* __restrict__ stats,
                                                      const float* __restrict__ g,
                                                      const float* __restrict__ b,
                                                      float* __restrict__ out)
{
    int idx = blockIdx.x * blockDim.x + threadIdx.x;
    if (idx >= TOTAL) return;
    int t = idx % Tt;
    int v = (idx / Tt) % Vv;
    int c = (idx / (Tt * Vv)) % Cc;
    int bb = idx / (Tt * Vv * Cc);
    float f = F[(size_t)((bb * Tt + t) * Vv + v) * Cc + c];
    const float inv = 1.0f / Pp;
    float mean = stats[c] * inv;
    float var = stats[Cc + c] * inv - mean * mean;
    float val = (f - mean) * rsqrtf(var + 1e-5f) * g[c] + b[c];
    out[idx] = val > 0.f ? val : 0.01f * val;
}

// ---------------- graph attention (7 slots); residual from hi/lo xn ----------------
__global__ void __launch_bounds__(256) attn_j(const float* __restrict__ QKV,
                                              const float* __restrict__ AKV,
                                              const float* __restrict__ AKVr,
                                              const __half* __restrict__ xnh,
                                              const __half* __restrict__ xnl,
                                              float* __restrict__ y1,
                                              float* __restrict__ zstats)
{
    int p = blockIdx.x;
    int co = threadIdx.x;
    if (p == 0) { zstats[co] = 0.f; zstats[256 + co] = 0.f; }   // fold bn_zero
    int n = p / Vv, l = p - n * Vv;
    size_t qbase = (size_t)p * 768 + co;
    size_t abase = (size_t)p * 512 + co;
    size_t rbase = (size_t)n * 512 + co;
    float q = QKV[qbase];
    int deg = c_deg[l];
    float sc[7];
    #pragma unroll
    for (int w = 0; w < 5; w++) {
        float d = -1e30f;
        if (w < deg) {
            int j = c_nbr[l][w];
            float dd = q * QKV[(size_t)(n * Vv + j) * 768 + 256 + co];
            #pragma unroll
            for (int o = 16; o; o >>= 1) dd += __shfl_xor_sync(~0u, dd, o);
            d = dd * INV_SQRT_DK;
        }
        sc[w] = d;
    }
    {
        float dd = q * AKV[abase];
        #pragma unroll
        for (int o = 16; o; o >>= 1) dd += __shfl_xor_sync(~0u, dd, o);
        sc[5] = dd * INV_SQRT_DK;
        dd = q * AKVr[rbase];
        #pragma unroll
        for (int o = 16; o; o >>= 1) dd += __shfl_xor_sync(~0u, dd, o);
        sc[6] = dd * INV_SQRT_DK;
    }
    float mx = sc[0];
    #pragma unroll
    for (int w = 1; w < 7; w++) mx = fmaxf(mx, sc[w]);
    float wg[7];
    float sum = 0.f;
    #pragma unroll
    for (int w = 0; w < 7; w++) { wg[w] = expf(sc[w] - mx); sum += wg[w]; }
    float att = 0.f;
    #pragma unroll
    for (int w = 0; w < 5; w++)
        if (w < deg) att += wg[w] * QKV[(size_t)(n * Vv + c_nbr[l][w]) * 768 + 512 + co];
    att += wg[5] * AKV[abase + 256] + wg[6] * AKVr[rbase + 256];
    size_t xo = (size_t)p * Cc + co;
    float xnv = __half2float(xnh[xo]) + __half2float(xnl[xo]);
    y1[xo] = xnv + att / sum;
}

// ---------------- BatchNorm (axes 0,2) ----------------
__global__ void __launch_bounds__(256) bn_stats(const float* __restrict__ x,
                                                float* __restrict__ stats, int rows)
{
    int c = threadIdx.x;
    int r0 = blockIdx.x * 64;
    float s = 0.f, s2 = 0.f;
    for (int r = r0; r < r0 + 64; r++) {
        float v = x[(size_t)r * Cc + c];
        s += v; s2 += v * v;
    }
    atomicAdd(&stats[c], s);
    atomicAdd(&stats[Cc + c], s2);
}

__global__ void __launch_bounds__(256) bn_apply(const float* __restrict__ x,
                                                const float* __restrict__ stats,
                                                const float* __restrict__ g,
                                                const float* __restrict__ b,
                                                __half* __restrict__ yh,
                                                __half* __restrict__ yl,
                                                int rows, int leaky)
{
    int idx = blockIdx.x * blockDim.x + threadIdx.x;
    if (idx >= rows * Cc) return;
    int c = idx & 255;
    float inv = 1.0f / rows;
    float mean = stats[c] * inv;
    float var = stats[Cc + c] * inv - mean * mean;
    float v = (x[idx] - mean) * rsqrtf(var + 1e-5f) * g[c] + b[c];
    if (leaky) v = v > 0.f ? v : 0.01f * v;
    f2hl(v, yh[idx], yl[idx]);
}

// ---------------- host ----------------
template <typename Sym>
static float* sym_f(const Sym& s) { void* p = nullptr; cudaGetSymbolAddress(&p, s); return (float*)p; }
template <typename Sym>
static __half* sym_h(const Sym& s) { void* p = nullptr; cudaGetSymbolAddress(&p, s); return (__half*)p; }

extern "C" void kernel_launch(void* const* d_in, const int* in_sizes, int n_in,
                              void* d_out, int out_size)
{
    const float* data  = (const float*)d_in[0];
    const float* ln_g  = (const float*)d_in[1];
    const float* ln_b  = (const float*)d_in[2];
    const float* jq_w  = (const float*)d_in[3];
    const float* jq_b  = (const float*)d_in[4];
    const float* jk_w  = (const float*)d_in[5];
    const float* jk_b  = (const float*)d_in[6];
    const float* jv_w  = (const float*)d_in[7];
    const float* jv_b  = (const float*)d_in[8];
    const float* jbn_g = (const float*)d_in[9];
    const float* jbn_b = (const float*)d_in[10];
    const float* jf1_w = (const float*)d_in[11];
    const float* jf1_b = (const float*)d_in[12];
    const float* jf2_w = (const float*)d_in[13];
    const float* jf2_b = (const float*)d_in[14];
    const float* jfbn_g = (const float*)d_in[15];
    const float* jfbn_b = (const float*)d_in[16];
    // relay-path weights (d_in[17..30]) are dead: relay never feeds back into nodes.

    float* X    = sym_f(g_X);
    float* QKV  = sym_f(g_QKV);
    float* AKV  = sym_f(g_AKV);
    float* AKVr = sym_f(g_AKVr);
    float* y1   = sym_f(g_y1);
    float* F    = sym_f(g_F);
    float* bj   = sym_f(g_bj);
    float* stats = sym_f(g_stats);
    __half *Eh = sym_h(g_Eh), *El = sym_h(g_El);
    __half *Rh = sym_h(g_Rh), *Rl = sym_h(g_Rl);
    __half *xnh = sym_h(g_xnh), *xnl = sym_h(g_xnl);
    __half *reth = sym_h(g_reth), *retl = sym_h(g_retl);
    __half *Hh = sym_h(g_Hh), *Hl = sym_h(g_Hl);
    __half *Wj = sym_h(g_Wj);
    __half *F1 = sym_h(g_F1);
    __half *F2 = sym_h(g_F2);

    static bool attr_set = false;
    if (!attr_set) {
        cudaFuncSetAttribute(gemm_mma, cudaFuncAttributeMaxDynamicSharedMemorySize, GEMM_SMEM);
        cudaFuncSetAttribute(gemm_proj3, cudaFuncAttributeMaxDynamicSharedMemorySize, GEMM_SMEM);
        attr_set = true;
    }

    prep_kernel<<<(TOTAL + 255) / 256, 256>>>(data, X, Eh, El);
    relay_init_kernel<<<(Nr * Cc + 255) / 256, 256>>>(X, Rh, Rl);

    wprep2<<<(2 * WPREP_TOTAL + 255) / 256, 256>>>(
        jq_w, jk_w, jv_w, jq_b, jk_b, jv_b, jf1_w, jf2_w,
        Wj, bj, F1, F2);

    // layer-0 entry LN reads X
    ln_kernel<<<Pp / 8, 256>>>(X, ln_g, ln_b, xnh, xnl);

    for (int ly = 0; ly < 2; ly++) {
        const __half* Wl = Wj + (size_t)ly * 3 * Cc * Cc;
        const float* bl  = bj + (size_t)ly * 3 * Cc;
        const float* bng = jbn_g + ly * Cc;
        const float* bnb = jbn_b + ly * Cc;
        const __half* f1p = F1 + (size_t)ly * DIN * Cc;
        const float* f1b = jf1_b + ly * DIN;
        const __half* f2p = F2 + (size_t)ly * Cc * DIN;
        const float* f2b = jf2_b + ly * Cc;
        const float* fbg = jfbn_g + ly * Cc;
        const float* fbb = jfbn_b + ly * Cc;

        // all three projections in ONE launch (QKV | AKV | AKVr)
        gemm_proj3<<<PROJ_BLOCKS, 256, GEMM_SMEM>>>(
            xnh, xnl, Eh, El, Rh, Rl, Wl, bl, QKV, AKV, AKVr);

        attn_j<<<Pp, 256>>>(QKV, AKV, AKVr, xnh, xnl, y1, stats);  // zeroes stats (block 0)

        bn_stats<<<Pp / 64, 256>>>(y1, stats, Pp);
        bn_apply<<<(Pp * Cc + 255) / 256, 256>>>(y1, stats, bng, bnb, reth, retl, Pp, 0);

        // FFN1: H = relu(ret @ f1^T + b1), written directly as hi/lo fp16
        gemm_mma<<<dim3(DIN / 128, Pp / 64), 256, GEMM_SMEM>>>(
            reth, retl, f1p, f1b, nullptr, nullptr, nullptr, Hh, Hl, DIN, Cc, 1, nullptr);
        // FFN2: F = H @ f2^T + b2 + ret(hi/lo)  (block (0,0) zeroes stats for next bn_stats)
        gemm_mma<<<dim3(Cc / 128, Pp / 64), 256, GEMM_SMEM>>>(
            Hh, Hl, f2p, f2b, reth, retl, F, nullptr, nullptr, Cc, DIN, 0, stats);

        bn_stats<<<Pp / 64, 256>>>(F, stats, Pp);

        if (ly == 0) {
            // fused BN(leaky)+LN into next layer's normalized input (no X round-trip)
            bnln_kernel<<<Pp / 8, 256>>>(F, stats, fbg, fbb,
                                         ln_g + Cc, ln_b + Cc, xnh, xnl);
        } else {
            // fused BN(leaky)+transpose to output
            bnfinal_kernel<<<(TOTAL + 255) / 256, 256>>>(F, stats, fbg, fbb,
                                                         (float*)d_out);
        }
    }
}